// round 6
// baseline (speedup 1.0000x reference)
#include <cuda_runtime.h>
#include <cstdint>

// CARAFE: N=4, C=256, H=W=64, K=5, G=1, S=2  ->  out [4,256,128,128] f32
#define KK   5
#define N_   4
#define C_   256
#define H_   64
#define W_   64
#define HO   128
#define WO   128

#define TH_CELLS 4         // input cells per CTA (rows)
#define TW_CELLS 8         // input cells per CTA (cols)
#define PR 8               // patch rows = TH_CELLS + 4
#define PC 12              // patch cols = TW_CELLS + 4
#define PS 13              // row stride in float2 units (odd stagger)
#define PAIR_F (PR * PS * 2)      // 208 floats per channel-pair patch
#define STAGE_F (4 * PAIR_F)      // 832 floats per 8-channel stage
#define NTHREADS 128
#define NSTAGE 32                 // all 256 channels in one CTA (masks read once)
#define NLOAD (8 * PR * PC)       // 768 feature elements per stage
#define LPT (NLOAD / NTHREADS)    // 6

typedef unsigned long long ull;

__device__ __forceinline__ ull pack2(float lo, float hi) {
    ull r;
    asm("mov.b64 %0, {%1, %2};" : "=l"(r) : "f"(lo), "f"(hi));
    return r;
}
__device__ __forceinline__ void unpack2(float& lo, float& hi, ull v) {
    asm("mov.b64 {%0, %1}, %2;" : "=f"(lo), "=f"(hi) : "l"(v));
}
__device__ __forceinline__ void ffma2(ull& d, ull a, ull b) {
    asm("fma.rn.f32x2 %0, %1, %2, %0;" : "+l"(d) : "l"(a), "l"(b));
}

__global__ void __launch_bounds__(NTHREADS, 4)
carafe_kernel(const float* __restrict__ feat, const float* __restrict__ masks,
              float* __restrict__ out)
{
    __shared__ __align__(16) float sbuf[2][STAGE_F];   // 6656 B

    const int t    = threadIdx.x;
    const int cid  = t & 31;          // cell in 4x8 tile
    const int row  = (t >> 5) & 1;    // output sub-row p within cell
    const int half = t >> 6;          // 0: pairs {0,1} (ch0..3)  1: pairs {2,3} (ch4..7)
    const int hh   = cid >> 3;        // 0..3
    const int ww   = cid & 7;         // 0..7

    const int b    = blockIdx.x;      // 0..511
    const int n    = b >> 7;
    const int tidx = b & 127;
    const int th   = tidx >> 3;       // 0..15
    const int tw   = tidx & 7;        // 0..7
    const int h0   = th * TH_CELLS;
    const int w0   = tw * TW_CELLS;
    const int oh   = (h0 + hh) * 2 + row;
    const int ow0  = (w0 + ww) * 2;   // even -> 8B-aligned float2 in masks/out

    // ---- per-thread masks: 25 taps, q-pair (ow0, ow0+1) per tap ----
    float2 m[25];
    {
        const float* mb = masks + (size_t)n * 25 * (HO * WO) + (size_t)oh * WO + ow0;
        #pragma unroll
        for (int k = 0; k < 25; ++k)
            m[k] = __ldg((const float2*)(mb + (size_t)k * (HO * WO)));
    }

    // ---- cooperative-load slots: interleaved (ch&1) channel-pair layout ----
    const float* fbase = feat + (size_t)n * (C_ * H_ * W_);
    int sofs[LPT], gofs[LPT];
    #pragma unroll
    for (int i = 0; i < LPT; ++i) {
        const int e   = t + i * NTHREADS;          // < 768
        const int ch  = e / (PR * PC);
        const int rem = e - ch * (PR * PC);
        const int r   = rem / PC;
        const int col = rem - r * PC;
        const int gr  = h0 - 2 + r;
        const int gc  = w0 - 2 + col;
        sofs[i] = (ch >> 1) * PAIR_F + r * (PS * 2) + col * 2 + (ch & 1);
        gofs[i] = ((unsigned)gr < (unsigned)H_ && (unsigned)gc < (unsigned)W_)
                      ? (ch * (H_ * W_) + gr * W_ + gc)
                      : -1;
    }

    float v[LPT];

    // prologue: stage 0 -> buffer 0
    #pragma unroll
    for (int i = 0; i < LPT; ++i)
        v[i] = (gofs[i] >= 0) ? __ldg(fbase + gofs[i]) : 0.f;
    #pragma unroll
    for (int i = 0; i < LPT; ++i)
        sbuf[0][sofs[i]] = v[i];
    __syncthreads();

    float* obase = out + (size_t)n * (C_ * HO * WO) + (size_t)oh * WO + ow0;

    for (int s = 0; s < NSTAGE; ++s) {
        // prefetch next stage's features
        if (s + 1 < NSTAGE) {
            const float* fb = fbase + (size_t)(s + 1) * 8 * (H_ * W_);
            #pragma unroll
            for (int i = 0; i < LPT; ++i)
                v[i] = (gofs[i] >= 0) ? __ldg(fb + gofs[i]) : 0.f;
        }

        // compute: 2 channel pairs x q-pair, 25 taps
        // per tap: 2x LDS.64 + 2 mask dups + 4 FFMA2  (16 B smem -> 8 FMA)
        const float* sb = &sbuf[s & 1][0] + (2 * half) * PAIR_F + hh * (PS * 2) + ww * 2;
        ull a0q0 = 0, a0q1 = 0, a1q0 = 0, a1q1 = 0;
        #pragma unroll
        for (int ki = 0; ki < KK; ++ki) {
            #pragma unroll
            for (int kj = 0; kj < KK; ++kj) {
                const int k   = ki * KK + kj;
                const int off = ki * (PS * 2) + kj * 2;
                const ull f0 = *(const ull*)(sb + off);            // ch pair 2*half
                const ull f1 = *(const ull*)(sb + PAIR_F + off);   // ch pair 2*half+1
                const ull dq0 = pack2(m[k].x, m[k].x);
                const ull dq1 = pack2(m[k].y, m[k].y);
                ffma2(a0q0, f0, dq0);
                ffma2(a0q1, f0, dq1);
                ffma2(a1q0, f1, dq0);
                ffma2(a1q1, f1, dq1);
            }
        }

        // stores: 4 channels x q-pair, STG.64 coalesced
        {
            const int c0 = s * 8 + 4 * half;
            float l0, h0v, l1, h1v;
            unpack2(l0, h0v, a0q0);
            unpack2(l1, h1v, a0q1);
            *(ull*)(obase + (size_t)(c0 + 0) * (HO * WO)) = pack2(l0, l1);
            *(ull*)(obase + (size_t)(c0 + 1) * (HO * WO)) = pack2(h0v, h1v);
            unpack2(l0, h0v, a1q0);
            unpack2(l1, h1v, a1q1);
            *(ull*)(obase + (size_t)(c0 + 2) * (HO * WO)) = pack2(l0, l1);
            *(ull*)(obase + (size_t)(c0 + 3) * (HO * WO)) = pack2(h0v, h1v);
        }

        // commit prefetched data to the other buffer
        if (s + 1 < NSTAGE) {
            float* dst = &sbuf[(s + 1) & 1][0];
            #pragma unroll
            for (int i = 0; i < LPT; ++i)
                dst[sofs[i]] = v[i];
        }
        __syncthreads();
    }
}

extern "C" void kernel_launch(void* const* d_in, const int* in_sizes, int n_in,
                              void* d_out, int out_size) {
    const float* feat  = (const float*)d_in[0];
    const float* masks = (const float*)d_in[1];
    if (n_in >= 2 && in_sizes[0] == N_ * KK * KK * HO * WO &&
        in_sizes[1] == N_ * C_ * H_ * W_) {
        const float* tmp = feat; feat = masks; masks = tmp;
    }
    carafe_kernel<<<N_ * 128, NTHREADS>>>(feat, masks, (float*)d_out);
}